// round 6
// baseline (speedup 1.0000x reference)
// Round 6 resubmission: R2 and R5 (cudaErrorDevicesUnavailable at harness init,
// compute-exclusive conflict), R3 and R4 (broker acquisition timeouts) were all
// infra failures before any kernel instruction executed. R0/R1 ran fine with the
// same 131MB device-global, so this is pool contention, not kernel content.
// Kernel body byte-identical to R2-R5 (fp64-alpha scaled-linear CTC).
#include <cuda_runtime.h>
#include <cstdint>

#define BB 64
#define TT 2000
#define VV 256
#define SS 400
#define LDIM 801          // 2*S+1
#define NTH 832           // 26 warps, one state per thread
#define NWARP 26

// Scratch (device globals: no allocation allowed)
__device__ float g_P[(size_t)BB * TT * VV];   // exp(log_probs), 131 MB
__device__ float g_loss[BB];

// ---------------------------------------------------------------------------
// Packed f32x2 exp helper: exp(x) for x <= 0 via degree-4 exp2 polynomial,
// exponent inserted with the magic-constant bit trick. Two elements per op.
// ---------------------------------------------------------------------------
__device__ __forceinline__ unsigned long long pk2(float lo, float hi) {
    unsigned long long r;
    asm("mov.b64 %0, {%1, %2};" : "=l"(r) : "f"(lo), "f"(hi));
    return r;
}
__device__ __forceinline__ void upk2(unsigned long long v, float& lo, float& hi) {
    asm("mov.b64 {%0, %1}, %2;" : "=f"(lo), "=f"(hi) : "l"(v));
}

__device__ __forceinline__ void exp_pair(float x0, float x1, float& r0, float& r1) {
    x0 = fmaxf(x0, -87.0f);
    x1 = fmaxf(x1, -87.0f);
    unsigned long long x = pk2(x0, x1);
    const unsigned long long L2E  = pk2(1.4426950408889634f, 1.4426950408889634f);
    const unsigned long long MAG  = pk2(12582912.0f, 12582912.0f);   // 1.5 * 2^23
    const unsigned long long NMAG = pk2(-12582912.0f, -12582912.0f);
    const unsigned long long NONE = pk2(-1.0f, -1.0f);
    const unsigned long long C4 = pk2(0.00961812911f, 0.00961812911f);
    const unsigned long long C3 = pk2(0.05550410866f, 0.05550410866f);
    const unsigned long long C2 = pk2(0.24022650696f, 0.24022650696f);
    const unsigned long long C1 = pk2(0.69314718056f, 0.69314718056f);
    const unsigned long long ONE = pk2(1.0f, 1.0f);

    unsigned long long y, z, fi, f, p;
    asm("mul.rn.f32x2 %0, %1, %2;"     : "=l"(y)  : "l"(x),  "l"(L2E));
    asm("add.rn.f32x2 %0, %1, %2;"     : "=l"(z)  : "l"(y),  "l"(MAG));   // round to int
    asm("add.rn.f32x2 %0, %1, %2;"     : "=l"(fi) : "l"(z),  "l"(NMAG));  // i as float
    asm("fma.rn.f32x2 %0, %1, %2, %3;" : "=l"(f)  : "l"(fi), "l"(NONE), "l"(y)); // f = y - i
    asm("fma.rn.f32x2 %0, %1, %2, %3;" : "=l"(p)  : "l"(f), "l"(C4), "l"(C3));
    asm("fma.rn.f32x2 %0, %1, %2, %3;" : "=l"(p)  : "l"(f), "l"(p),  "l"(C2));
    asm("fma.rn.f32x2 %0, %1, %2, %3;" : "=l"(p)  : "l"(f), "l"(p),  "l"(C1));
    asm("fma.rn.f32x2 %0, %1, %2, %3;" : "=l"(p)  : "l"(f), "l"(p),  "l"(ONE));

    float pf0, pf1, zf0, zf1;
    upk2(p, pf0, pf1);
    upk2(z, zf0, zf1);
    // result_bits = poly_bits + (z_bits << 23)  (adds 2^i exactly; magic bits shift out)
    r0 = __uint_as_float(__float_as_uint(pf0) + (__float_as_uint(zf0) << 23));
    r1 = __uint_as_float(__float_as_uint(pf1) + (__float_as_uint(zf1) << 23));
}

// ---------------------------------------------------------------------------
// Kernel 1: P = exp(log_probs). Split between MUFU (__expf) and packed-FMA
// polynomial so neither pipe alone bounds throughput.
// ---------------------------------------------------------------------------
__global__ void exp_kernel(const float* __restrict__ lp) {
    const float4* in  = (const float4*)lp;
    float4*       out = (float4*)g_P;
    const int64_t n4 = (int64_t)BB * TT * VV / 4;
    int64_t i  = (int64_t)blockIdx.x * blockDim.x + threadIdx.x;
    int64_t st = (int64_t)gridDim.x * blockDim.x;
    for (; i < n4; i += st) {
        float4 v = in[i];
        float4 r;
        exp_pair(v.x, v.y, r.x, r.y);   // FMA/ALU pipes
        r.z = __expf(v.z);              // MUFU pipe
        r.w = __expf(v.w);              // MUFU pipe
        out[i] = r;
    }
}

// ---------------------------------------------------------------------------
// Kernel 2: CTC forward, scaled linear domain with FP64 alpha (the ~250-bit
// dynamic-range spread between sum-dominant and answer-relevant lattice
// states overflows fp32's window; fp64's 2046-bit window is safe).
// One CTA per batch element, one thread per lattice state.
// ---------------------------------------------------------------------------
__device__ __forceinline__ double warp_sum_d(double v) {
    v += __shfl_xor_sync(0xffffffffu, v, 16);
    v += __shfl_xor_sync(0xffffffffu, v, 8);
    v += __shfl_xor_sync(0xffffffffu, v, 4);
    v += __shfl_xor_sync(0xffffffffu, v, 2);
    v += __shfl_xor_sync(0xffffffffu, v, 1);
    return v;
}

__global__ __launch_bounds__(NTH, 1) void ctc_kernel(const int* __restrict__ targets,
                                                     const int* __restrict__ in_len,
                                                     const int* __restrict__ tg_len) {
    __shared__ double buf[2][LDIM + 2];             // double-buffered alpha, 2-pad left
    __shared__ __align__(16) float prow[8][VV];     // 8-deep ring of P rows
    __shared__ double warp_sums[NWARP];
    __shared__ double sh_scale;

    const int b    = blockIdx.x;
    const int tid  = threadIdx.x;
    const int l    = tid;
    const int lane = tid & 31;
    const int wid  = tid >> 5;
    const int tlen = tg_len[b];
    const int ilen = in_len[b];
    const int Lv   = 2 * tlen + 1;
    const bool inL = (l < LDIM);
    const bool act = (l < Lv);

    // ext symbol + skip-connection flag (registers, constant over t)
    int  ext  = 1;        // BLANK
    bool skip = false;
    if (inL && (l & 1)) {
        ext = targets[b * SS + (l >> 1)];
        int prev = (l >= 3) ? targets[b * SS + (l >> 1) - 1] : -1;
        skip = (ext != prev);
    }

    // zero both alpha buffers (incl. padding)
    for (int i = tid; i < 2 * (LDIM + 2); i += NTH) (&buf[0][0])[i] = 0.0;

    const float* Pb = g_P + (size_t)b * TT * VV;

    // preload rows 0..5 into the ring (row r -> slot r)
    if (tid < 64) {
        #pragma unroll
        for (int r = 0; r < 6; ++r)
            ((float4*)prow[r])[tid] = ((const float4*)(Pb + r * VV))[tid];
    }
    __syncthreads();

    // t = 0 init
    double a = 0.0;
    if (l == 0) a = (double)prow[0][1];
    else if (l == 1) a = (double)prow[0][ext];
    if (l < 2) buf[0][2 + l] = a;
    __syncthreads();

    int e_cum = 0;  // only thread 0's copy matters
    unsigned sbase = (unsigned)__cvta_generic_to_shared(&prow[0][0]);

    for (int t = 1; t < ilen; ++t) {
        // prefetch row t+5 (distance 5 ~ 750 cyc, hides DRAM latency)
        if (tid < 64) {
            int rp = t + 5;
            if (rp < ilen) {
                unsigned dst = sbase + (unsigned)(((rp & 7) * VV + tid * 4) * 4);
                const float* src = Pb + (size_t)rp * VV + tid * 4;
                asm volatile("cp.async.cg.shared.global [%0], [%1], 16;" :: "r"(dst), "l"(src));
            }
            asm volatile("cp.async.commit_group;");
        }

        const float*  rowp = prow[t & 7];
        const double* pbuf = buf[(t - 1) & 1];
        double nv = 0.0;
        if (act) {
            double a1 = pbuf[2 + l - 1];
            double a2 = skip ? pbuf[2 + l - 2] : 0.0;
            nv = ((a + a1) + a2) * (double)rowp[ext];
        }

        const int ph = t & 15;                 // renorm cadence: 16 steps
        if (ph == 2 && t > 5) {                // apply scale computed 1 step ago
            double sc = sh_scale;
            nv *= sc;
            if (tid == 0) {
                int esc = (__double2hiint(sc) >> 20) & 0x7FF;
                e_cum += 1023 - esc;
            }
        }

        if (inL) buf[t & 1][2 + l] = nv;
        a = nv;

        if (ph == 0) {                          // reduce: per-warp partial sums
            double s = warp_sum_d(nv);
            if (lane == 0) warp_sums[wid] = s;
        } else if (ph == 1 && t > 4 && wid == 0) {  // combine: warp 0 only
            double s = (lane < NWARP) ? warp_sums[lane] : 0.0;
            s = warp_sum_d(s);
            if (lane == 0) {
                int ef = (__double2hiint(s) >> 20) & 0x7FF;
                double sc = 1.0;
                int esc = 2046 - ef;            // normalize sum exponent to ~2^0
                if (ef < 2046 && esc > 0 && esc < 2047)
                    sc = __hiloint2double(esc << 20, 0);
                sh_scale = sc;
            }
        }

        if (tid < 64) asm volatile("cp.async.wait_group 4;");
        __syncthreads();
    }

    if (tid < 64) asm volatile("cp.async.wait_group 0;");  // drain before exit

    if (tid == 0) {
        const double* fb = buf[(ilen - 1) & 1];
        double s = fb[2 + 2 * tlen] + fb[2 + 2 * tlen - 1];
        double ll = log(s) + (double)e_cum * 0.6931471805599453;
        float loss = (float)(-ll);
        if (!(loss < 1e29f)) loss = 0.0f;      // infeasible guard (matches reference)
        g_loss[b] = loss / (float)tlen;
    }
}

// ---------------------------------------------------------------------------
// Kernel 3: deterministic fixed-tree mean over 64 losses.
// ---------------------------------------------------------------------------
__global__ void finalize_kernel(float* __restrict__ out) {
    int lane = threadIdx.x;
    float v = g_loss[lane] + g_loss[lane + 32];
    v += __shfl_xor_sync(0xffffffffu, v, 16);
    v += __shfl_xor_sync(0xffffffffu, v, 8);
    v += __shfl_xor_sync(0xffffffffu, v, 4);
    v += __shfl_xor_sync(0xffffffffu, v, 2);
    v += __shfl_xor_sync(0xffffffffu, v, 1);
    if (lane == 0) out[0] = v * (1.0f / (float)BB);
}

extern "C" void kernel_launch(void* const* d_in, const int* in_sizes, int n_in,
                              void* d_out, int out_size) {
    const float* lp = (const float*)d_in[0];
    const int*   tg = (const int*)d_in[1];
    const int*   il = (const int*)d_in[2];
    const int*   tl = (const int*)d_in[3];

    exp_kernel<<<3072, 256>>>(lp);
    ctc_kernel<<<BB, NTH>>>(tg, il, tl);
    finalize_kernel<<<1, 32>>>((float*)d_out);
}

// round 8
// speedup vs baseline: 4.4898x; 4.4898x over previous
// R8 resubmission: R7 never ran (broker acquisition timeout). Body byte-identical
// to R7: per-state software extended-range fp32 (m in [1,2) + int32 exponent)
// replacing fp64 alpha. GB300 vector FP64 measured ~1.3 lane-ops/cyc/SM in R6
// (ctc ~1900 cyc/step); fma/alu pipes run 64 lanes/cyc/SM each.
#include <cuda_runtime.h>
#include <cstdint>

#define BB 64
#define TT 2000
#define VV 256
#define SS 400
#define LDIM 801          // 2*S+1
#define NTH 832           // 26 warps, one state per thread
#define ENEG (-(1 << 29)) // exponent marker for zero states

// Scratch (device globals: no allocation allowed)
__device__ float g_P[(size_t)BB * TT * VV];   // exp(log_probs), 131 MB
__device__ float g_loss[BB];

// ---------------------------------------------------------------------------
// Packed f32x2 exp helper (unchanged; exp_kernel measured at LTS cap, 37us)
// ---------------------------------------------------------------------------
__device__ __forceinline__ unsigned long long pk2(float lo, float hi) {
    unsigned long long r;
    asm("mov.b64 %0, {%1, %2};" : "=l"(r) : "f"(lo), "f"(hi));
    return r;
}
__device__ __forceinline__ void upk2(unsigned long long v, float& lo, float& hi) {
    asm("mov.b64 {%0, %1}, %2;" : "=f"(lo), "=f"(hi) : "l"(v));
}

__device__ __forceinline__ void exp_pair(float x0, float x1, float& r0, float& r1) {
    x0 = fmaxf(x0, -87.0f);
    x1 = fmaxf(x1, -87.0f);
    unsigned long long x = pk2(x0, x1);
    const unsigned long long L2E  = pk2(1.4426950408889634f, 1.4426950408889634f);
    const unsigned long long MAG  = pk2(12582912.0f, 12582912.0f);   // 1.5 * 2^23
    const unsigned long long NMAG = pk2(-12582912.0f, -12582912.0f);
    const unsigned long long NONE = pk2(-1.0f, -1.0f);
    const unsigned long long C4 = pk2(0.00961812911f, 0.00961812911f);
    const unsigned long long C3 = pk2(0.05550410866f, 0.05550410866f);
    const unsigned long long C2 = pk2(0.24022650696f, 0.24022650696f);
    const unsigned long long C1 = pk2(0.69314718056f, 0.69314718056f);
    const unsigned long long ONE = pk2(1.0f, 1.0f);

    unsigned long long y, z, fi, f, p;
    asm("mul.rn.f32x2 %0, %1, %2;"     : "=l"(y)  : "l"(x),  "l"(L2E));
    asm("add.rn.f32x2 %0, %1, %2;"     : "=l"(z)  : "l"(y),  "l"(MAG));   // round to int
    asm("add.rn.f32x2 %0, %1, %2;"     : "=l"(fi) : "l"(z),  "l"(NMAG));  // i as float
    asm("fma.rn.f32x2 %0, %1, %2, %3;" : "=l"(f)  : "l"(fi), "l"(NONE), "l"(y)); // f = y - i
    asm("fma.rn.f32x2 %0, %1, %2, %3;" : "=l"(p)  : "l"(f), "l"(C4), "l"(C3));
    asm("fma.rn.f32x2 %0, %1, %2, %3;" : "=l"(p)  : "l"(f), "l"(p),  "l"(C2));
    asm("fma.rn.f32x2 %0, %1, %2, %3;" : "=l"(p)  : "l"(f), "l"(p),  "l"(C1));
    asm("fma.rn.f32x2 %0, %1, %2, %3;" : "=l"(p)  : "l"(f), "l"(p),  "l"(ONE));

    float pf0, pf1, zf0, zf1;
    upk2(p, pf0, pf1);
    upk2(z, zf0, zf1);
    r0 = __uint_as_float(__float_as_uint(pf0) + (__float_as_uint(zf0) << 23));
    r1 = __uint_as_float(__float_as_uint(pf1) + (__float_as_uint(zf1) << 23));
}

__global__ void exp_kernel(const float* __restrict__ lp) {
    const float4* in  = (const float4*)lp;
    float4*       out = (float4*)g_P;
    const int64_t n4 = (int64_t)BB * TT * VV / 4;
    int64_t i  = (int64_t)blockIdx.x * blockDim.x + threadIdx.x;
    int64_t st = (int64_t)gridDim.x * blockDim.x;
    for (; i < n4; i += st) {
        float4 v = in[i];
        float4 r;
        exp_pair(v.x, v.y, r.x, r.y);   // FMA/ALU pipes
        r.z = __expf(v.z);              // MUFU pipe
        r.w = __expf(v.w);              // MUFU pipe
        out[i] = r;
    }
}

// ---------------------------------------------------------------------------
// Kernel 2: CTC forward. alpha[l] = (m, e): value = m * 2^e, m in [1,2) or 0.
// Per-state int exponents give unbounded dynamic range on fp32 pipes.
// One CTA per batch element, one thread per lattice state.
// ---------------------------------------------------------------------------
__global__ __launch_bounds__(NTH, 1) void ctc_kernel(const int* __restrict__ targets,
                                                     const int* __restrict__ in_len,
                                                     const int* __restrict__ tg_len) {
    __shared__ float2 buf[2][LDIM + 2];             // (m, e-as-float-bits), 2-pad left
    __shared__ __align__(16) float prow[8][VV];     // 8-deep ring of P rows

    const int b    = blockIdx.x;
    const int tid  = threadIdx.x;
    const int l    = tid;
    const int tlen = tg_len[b];
    const int ilen = in_len[b];
    const int Lv   = 2 * tlen + 1;
    const bool inL = (l < LDIM);
    const bool act = (l < Lv);

    // ext symbol + skip handling: skipbias pushes e2 far below any real
    // exponent when the skip transition is disallowed -> scale underflows to 0.
    int ext = 1;                  // BLANK
    int skipbias = -(1 << 28);    // disallowed by default
    if (inL && (l & 1)) {
        ext = targets[b * SS + (l >> 1)];
        int prev = (l >= 3) ? targets[b * SS + (l >> 1) - 1] : -1;
        if (ext != prev) skipbias = 0;
    }

    // init both alpha buffers (incl. padding) to zero-state
    for (int i = tid; i < 2 * (LDIM + 2); i += NTH)
        (&buf[0][0])[i] = make_float2(0.0f, __int_as_float(ENEG));

    const float* Pb = g_P + (size_t)b * TT * VV;

    // preload rows 0..5 into the ring
    if (tid < 64) {
        #pragma unroll
        for (int r = 0; r < 6; ++r)
            ((float4*)prow[r])[tid] = ((const float4*)(Pb + r * VV))[tid];
    }
    __syncthreads();

    // t = 0 init: alpha0[0] = P[0][blank], alpha0[1] = P[0][target[0]]
    float m0 = 0.0f; int e0 = ENEG;
    if (l < 2 && act) {
        float p = prow[0][(l == 0) ? 1 : ext];
        unsigned pb = __float_as_uint(p);
        e0 = (int)(pb >> 23) - 127;
        m0 = __uint_as_float((pb & 0x007FFFFFu) | 0x3F800000u);
        buf[0][2 + l] = make_float2(m0, __int_as_float(e0));
    }
    __syncthreads();

    unsigned sbase = (unsigned)__cvta_generic_to_shared(&prow[0][0]);

    for (int t = 1; t < ilen; ++t) {
        // prefetch row t+5 (distance 5 hides DRAM latency)
        if (tid < 64) {
            int rp = t + 5;
            if (rp < ilen) {
                unsigned dst = sbase + (unsigned)(((rp & 7) * VV + tid * 4) * 4);
                const float* src = Pb + (size_t)rp * VV + tid * 4;
                asm volatile("cp.async.cg.shared.global [%0], [%1], 16;" :: "r"(dst), "l"(src));
            }
            asm volatile("cp.async.commit_group;");
        }

        const float*  rowp = prow[t & 7];
        const float2* pbuf = buf[(t - 1) & 1];

        if (inL) {
            float2 v1 = pbuf[2 + l - 1];
            float2 v2 = pbuf[2 + l - 2];
            float m1 = v1.x; int e1 = __float_as_int(v1.y);
            float m2 = v2.x; int e2 = __float_as_int(v2.y) + skipbias;

            int emax = max(e0, max(e1, e2));
            int d0 = max(e0 - emax, -127);
            int d1 = max(e1 - emax, -127);
            int d2 = max(e2 - emax, -127);
            // 2^d: one IMAD each (d * 0x800000 + 0x3F800000); d=-127 -> 0.0f
            float s0 = __int_as_float((d0 + 127) << 23);
            float s1 = __int_as_float((d1 + 127) << 23);
            float s2 = __int_as_float((d2 + 127) << 23);

            float p = rowp[ext];
            float s = fmaf(m2, s2, fmaf(m1, s1, m0 * s0)) * p;

            unsigned sb = __float_as_uint(s);
            int en = emax + (int)(sb >> 23) - 127;
            float mn = __uint_as_float((sb & 0x007FFFFFu) | 0x3F800000u);
            if (s == 0.0f || !act) { mn = 0.0f; en = ENEG; }

            buf[t & 1][2 + l] = make_float2(mn, __int_as_float(en));
            m0 = mn; e0 = en;
        }

        if (tid < 64) asm volatile("cp.async.wait_group 4;");
        __syncthreads();
    }

    if (tid < 64) asm volatile("cp.async.wait_group 0;");  // drain before exit

    if (tid == 0) {
        const float2* fb = buf[(ilen - 1) & 1];
        float2 va = fb[2 + 2 * tlen];
        float2 vb = fb[2 + 2 * tlen - 1];
        int ea = __float_as_int(va.y), eb = __float_as_int(vb.y);
        int em = max(ea, eb);
        double s = (double)va.x * exp2((double)(ea - em))
                 + (double)vb.x * exp2((double)(eb - em));
        double ll = log(s) + (double)em * 0.6931471805599453;
        float loss = (float)(-ll);
        if (!(loss < 1e29f)) loss = 0.0f;      // infeasible guard (matches reference)
        g_loss[b] = loss / (float)tlen;
    }
}

// ---------------------------------------------------------------------------
// Kernel 3: deterministic fixed-tree mean over 64 losses.
// ---------------------------------------------------------------------------
__global__ void finalize_kernel(float* __restrict__ out) {
    int lane = threadIdx.x;
    float v = g_loss[lane] + g_loss[lane + 32];
    v += __shfl_xor_sync(0xffffffffu, v, 16);
    v += __shfl_xor_sync(0xffffffffu, v, 8);
    v += __shfl_xor_sync(0xffffffffu, v, 4);
    v += __shfl_xor_sync(0xffffffffu, v, 2);
    v += __shfl_xor_sync(0xffffffffu, v, 1);
    if (lane == 0) out[0] = v * (1.0f / (float)BB);
}

extern "C" void kernel_launch(void* const* d_in, const int* in_sizes, int n_in,
                              void* d_out, int out_size) {
    const float* lp = (const float*)d_in[0];
    const int*   tg = (const int*)d_in[1];
    const int*   il = (const int*)d_in[2];
    const int*   tl = (const int*)d_in[3];

    exp_kernel<<<3072, 256>>>(lp);
    ctc_kernel<<<BB, NTH>>>(tg, il, tl);
    finalize_kernel<<<1, 32>>>((float*)d_out);
}

// round 13
// speedup vs baseline: 6.0213x; 1.3411x over previous
// R13 resubmission: R9-R12 never ran (broker acquisition timeouts, infra
// failures #6-#9; last successful acquisition was R8). Body byte-identical:
// even/odd lattice split, (even,odd) state pair per thread in registers,
// odd states in smem (compacted float2), 416 threads / 13 warps.
#include <cuda_runtime.h>
#include <cstdint>

#define BB 64
#define TT 2000
#define VV 256
#define SS 400
#define NTH 416           // 13 warps, one (even,odd) state pair per thread
#define ENEG (-(1 << 29)) // exponent marker for zero states
#define SKIPOFF (-(1 << 28))

// Scratch (device globals: no allocation allowed)
__device__ float g_P[(size_t)BB * TT * VV];   // exp(log_probs), 131 MB
__device__ float g_loss[BB];

// ---------------------------------------------------------------------------
// Packed f32x2 exp helper (exp_kernel measured at LTS cap, ~36us: leave alone)
// ---------------------------------------------------------------------------
__device__ __forceinline__ unsigned long long pk2(float lo, float hi) {
    unsigned long long r;
    asm("mov.b64 %0, {%1, %2};" : "=l"(r) : "f"(lo), "f"(hi));
    return r;
}
__device__ __forceinline__ void upk2(unsigned long long v, float& lo, float& hi) {
    asm("mov.b64 {%0, %1}, %2;" : "=f"(lo), "=f"(hi) : "l"(v));
}

__device__ __forceinline__ void exp_pair(float x0, float x1, float& r0, float& r1) {
    x0 = fmaxf(x0, -87.0f);
    x1 = fmaxf(x1, -87.0f);
    unsigned long long x = pk2(x0, x1);
    const unsigned long long L2E  = pk2(1.4426950408889634f, 1.4426950408889634f);
    const unsigned long long MAG  = pk2(12582912.0f, 12582912.0f);   // 1.5 * 2^23
    const unsigned long long NMAG = pk2(-12582912.0f, -12582912.0f);
    const unsigned long long NONE = pk2(-1.0f, -1.0f);
    const unsigned long long C4 = pk2(0.00961812911f, 0.00961812911f);
    const unsigned long long C3 = pk2(0.05550410866f, 0.05550410866f);
    const unsigned long long C2 = pk2(0.24022650696f, 0.24022650696f);
    const unsigned long long C1 = pk2(0.69314718056f, 0.69314718056f);
    const unsigned long long ONE = pk2(1.0f, 1.0f);

    unsigned long long y, z, fi, f, p;
    asm("mul.rn.f32x2 %0, %1, %2;"     : "=l"(y)  : "l"(x),  "l"(L2E));
    asm("add.rn.f32x2 %0, %1, %2;"     : "=l"(z)  : "l"(y),  "l"(MAG));   // round to int
    asm("add.rn.f32x2 %0, %1, %2;"     : "=l"(fi) : "l"(z),  "l"(NMAG));  // i as float
    asm("fma.rn.f32x2 %0, %1, %2, %3;" : "=l"(f)  : "l"(fi), "l"(NONE), "l"(y)); // f = y - i
    asm("fma.rn.f32x2 %0, %1, %2, %3;" : "=l"(p)  : "l"(f), "l"(C4), "l"(C3));
    asm("fma.rn.f32x2 %0, %1, %2, %3;" : "=l"(p)  : "l"(f), "l"(p),  "l"(C2));
    asm("fma.rn.f32x2 %0, %1, %2, %3;" : "=l"(p)  : "l"(f), "l"(p),  "l"(C1));
    asm("fma.rn.f32x2 %0, %1, %2, %3;" : "=l"(p)  : "l"(f), "l"(p),  "l"(ONE));

    float pf0, pf1, zf0, zf1;
    upk2(p, pf0, pf1);
    upk2(z, zf0, zf1);
    r0 = __uint_as_float(__float_as_uint(pf0) + (__float_as_uint(zf0) << 23));
    r1 = __uint_as_float(__float_as_uint(pf1) + (__float_as_uint(zf1) << 23));
}

__global__ void exp_kernel(const float* __restrict__ lp) {
    const float4* in  = (const float4*)lp;
    float4*       out = (float4*)g_P;
    const int64_t n4 = (int64_t)BB * TT * VV / 4;
    int64_t i  = (int64_t)blockIdx.x * blockDim.x + threadIdx.x;
    int64_t st = (int64_t)gridDim.x * blockDim.x;
    for (; i < n4; i += st) {
        float4 v = in[i];
        float4 r;
        exp_pair(v.x, v.y, r.x, r.y);   // FMA/ALU pipes
        r.z = __expf(v.z);              // MUFU pipe
        r.w = __expf(v.w);              // MUFU pipe
        out[i] = r;
    }
}

// ---------------------------------------------------------------------------
// 2^d for d <= 0 with exact-zero cutoff below -127 (one max + one IMAD-shape)
// ---------------------------------------------------------------------------
__device__ __forceinline__ float sc2(int d) {
    d = max(d, -127);
    return __int_as_float((d + 127) << 23);
}

// ---------------------------------------------------------------------------
// Kernel 2: CTC forward, extended-range fp32 (m in [1,2) or 0, int exponent).
// Thread i owns states lo=2i (blank) and hi=2i+1 (symbol i) in registers.
// Only hi states are published to smem (compacted float2 -> conflict-free).
// Even (blank) states never skip and are never a skip source (l-2 of an odd
// state is odd) => lo update is 2-term, hi update is 3-term all-local.
// ---------------------------------------------------------------------------
__global__ __launch_bounds__(NTH, 1) void ctc_kernel(const int* __restrict__ targets,
                                                     const int* __restrict__ in_len,
                                                     const int* __restrict__ tg_len) {
    __shared__ float2 hibuf[2][NTH + 4];            // slot j+1 = hi state of thread j
    __shared__ __align__(16) float prow[8][VV];     // 8-deep ring of P rows
    __shared__ float2 sh_end;

    const int b    = blockIdx.x;
    const int tid  = threadIdx.x;
    const int i    = tid;
    const int tlen = tg_len[b];
    const int ilen = in_len[b];
    const bool act_lo = (i <= tlen);   // state 2i   < 2*tlen+1
    const bool act_hi = (i <  tlen);   // state 2i+1 < 2*tlen+1

    // hi-state symbol + skip bias (constant over t)
    int ext = 1, skipbias = SKIPOFF;
    if (i < SS) {
        ext = targets[b * SS + i];
        int prev = (i >= 1) ? targets[b * SS + i - 1] : -1;
        if (ext != prev) skipbias = 0;
    }

    // init both hi buffers (incl. pad slot 0) to zero-state (m=0 kills any leak)
    for (int k = tid; k < 2 * (NTH + 4); k += NTH)
        (&hibuf[0][0])[k] = make_float2(0.0f, __int_as_float(ENEG));

    const float* Pb = g_P + (size_t)b * TT * VV;

    // preload rows 0..5 into the ring
    if (tid < 64) {
        #pragma unroll
        for (int r = 0; r < 6; ++r)
            ((float4*)prow[r])[tid] = ((const float4*)(Pb + r * VV))[tid];
    }
    __syncthreads();

    // t = 0: alpha0[0] = P0[blank], alpha0[1] = P0[target0]
    float m_lo = 0.0f, m_hi = 0.0f;
    int   e_lo = ENEG,  e_hi = ENEG;
    if (i == 0) {
        unsigned pb = __float_as_uint(prow[0][1]);
        e_lo = (int)(pb >> 23) - 127;
        m_lo = __uint_as_float((pb & 0x007FFFFFu) | 0x3F800000u);
        unsigned ph = __float_as_uint(prow[0][ext]);
        e_hi = (int)(ph >> 23) - 127;
        m_hi = __uint_as_float((ph & 0x007FFFFFu) | 0x3F800000u);
        hibuf[0][1] = make_float2(m_hi, __int_as_float(e_hi));
    }
    __syncthreads();

    unsigned sbase = (unsigned)__cvta_generic_to_shared(&prow[0][0]);

    for (int t = 1; t < ilen; ++t) {
        // prefetch row t+5 (distance 5 hides DRAM latency)
        if (tid < 64) {
            int rp = t + 5;
            if (rp < ilen) {
                unsigned dst = sbase + (unsigned)(((rp & 7) * VV + tid * 4) * 4);
                const float* src = Pb + (size_t)rp * VV + tid * 4;
                asm volatile("cp.async.cg.shared.global [%0], [%1], 16;" :: "r"(dst), "l"(src));
            }
            asm volatile("cp.async.commit_group;");
        }

        const float*  rowp = prow[t & 7];
        const float2* hbp  = hibuf[(t - 1) & 1];
        float2*       hbc  = hibuf[t & 1];

        float2 nb = hbp[i];              // state 2i-1 (prev step); slot i, pad at 0
        float  p_b = rowp[1];            // broadcast blank prob
        float  p_s = rowp[ext];          // gathered symbol prob
        float  m1  = nb.x;
        int    e1  = __float_as_int(nb.y);

        // ---- lo (blank, 2-term: own + left odd neighbor) ----
        int   emx = max(e_lo, e1);
        float s   = fmaf(m_lo, sc2(e_lo - emx), m1 * sc2(e1 - emx)) * p_b;
        unsigned sb = __float_as_uint(s);
        int   nel = emx + (int)(sb >> 23) - 127;
        float nml = __uint_as_float((sb & 0x007FFFFFu) | 0x3F800000u);
        bool  zl  = (s == 0.0f) || !act_lo;

        // ---- hi (symbol, 3-term: own + own-lo + left odd neighbor w/ skip) ----
        int   e2  = e1 + skipbias;
        int   emh = max(e_hi, max(e_lo, e2));
        float sh  = fmaf(m_hi, sc2(e_hi - emh),
                    fmaf(m_lo, sc2(e_lo - emh), m1 * sc2(e2 - emh))) * p_s;
        unsigned sbh = __float_as_uint(sh);
        int   neh = emh + (int)(sbh >> 23) - 127;
        float nmh = __uint_as_float((sbh & 0x007FFFFFu) | 0x3F800000u);
        bool  zh  = (sh == 0.0f) || !act_hi;

        m_lo = zl ? 0.0f : nml;  e_lo = zl ? ENEG : nel;
        m_hi = zh ? 0.0f : nmh;  e_hi = zh ? ENEG : neh;

        hbc[i + 1] = make_float2(m_hi, __int_as_float(e_hi));

        if (tid < 64) asm volatile("cp.async.wait_group 4;");
        __syncthreads();
    }

    if (tid < 64) asm volatile("cp.async.wait_group 0;");  // drain before exit

    // readout: state 2*tlen = lo of thread tlen (registers); state 2*tlen-1 =
    // hi of thread tlen-1 = hibuf[(ilen-1)&1][tlen].
    if (i == tlen) sh_end = make_float2(m_lo, __int_as_float(e_lo));
    __syncthreads();

    if (tid == 0) {
        float2 va = sh_end;
        float2 vb = hibuf[(ilen - 1) & 1][tlen];
        int ea = __float_as_int(va.y), eb = __float_as_int(vb.y);
        int em = max(ea, eb);
        double ssum = (double)va.x * exp2((double)(ea - em))
                    + (double)vb.x * exp2((double)(eb - em));
        double ll = log(ssum) + (double)em * 0.6931471805599453;
        float loss = (float)(-ll);
        if (!(loss < 1e29f)) loss = 0.0f;      // infeasible guard (matches reference)
        g_loss[b] = loss / (float)tlen;
    }
}

// ---------------------------------------------------------------------------
// Kernel 3: deterministic fixed-tree mean over 64 losses.
// ---------------------------------------------------------------------------
__global__ void finalize_kernel(float* __restrict__ out) {
    int lane = threadIdx.x;
    float v = g_loss[lane] + g_loss[lane + 32];
    v += __shfl_xor_sync(0xffffffffu, v, 16);
    v += __shfl_xor_sync(0xffffffffu, v, 8);
    v += __shfl_xor_sync(0xffffffffu, v, 4);
    v += __shfl_xor_sync(0xffffffffu, v, 2);
    v += __shfl_xor_sync(0xffffffffu, v, 1);
    if (lane == 0) out[0] = v * (1.0f / (float)BB);
}

extern "C" void kernel_launch(void* const* d_in, const int* in_sizes, int n_in,
                              void* d_out, int out_size) {
    const float* lp = (const float*)d_in[0];
    const int*   tg = (const int*)d_in[1];
    const int*   il = (const int*)d_in[2];
    const int*   tl = (const int*)d_in[3];

    exp_kernel<<<3072, 256>>>(lp);
    ctc_kernel<<<BB, NTH>>>(tg, il, tl);
    finalize_kernel<<<1, 32>>>((float*)d_out);
}